// round 15
// baseline (speedup 1.0000x reference)
#include <cuda_runtime.h>
#include <cuda_bf16.h>
#include <math.h>
#include <stdint.h>

#define SEQ   2048
#define HDIM  2048
#define NH    16
#define QLR   1536
#define KVLR  512
#define NOPE  128
#define ROPEDIM 64
#define VHD   128
#define QHD   192   // NOPE + ROPE

// ---------------- scratch arena (no allocations allowed) ----------------
#define OFF_QLAT    0
#define OFF_KVLATPE (OFF_QLAT    + SEQ*QLR)
#define OFF_KVLAT   (OFF_KVLATPE + SEQ*(KVLR+ROPEDIM))
#define OFF_KPE     (OFF_KVLAT   + SEQ*KVLR)
#define OFF_Q       (OFF_KPE     + SEQ*ROPEDIM)
#define OFF_KV      (OFF_Q       + SEQ*NH*QHD)
#define OFF_ATTN    (OFF_KV      + SEQ*NH*(NOPE+VHD))
#define SCRATCH_TOTAL (OFF_ATTN  + SEQ*NH*VHD)

__device__ float g_scratch[SCRATCH_TOTAL];

// ---------------- tf32 helpers ----------------
__device__ __forceinline__ uint32_t f2tf32(float x) {
    uint32_t r;
    asm("cvt.rna.tf32.f32 %0, %1;" : "=r"(r) : "f"(x));
    return r;
}

__device__ __forceinline__ void split_tf32(float x, uint32_t& hi, uint32_t& lo) {
    hi = f2tf32(x);
    lo = f2tf32(x - __uint_as_float(hi));
}

__device__ __forceinline__ void mma_tf32(float4& d,
                                         uint32_t a0, uint32_t a1, uint32_t a2, uint32_t a3,
                                         uint32_t b0, uint32_t b1) {
    asm volatile(
        "mma.sync.aligned.m16n8k8.row.col.f32.tf32.tf32.f32 "
        "{%0,%1,%2,%3}, {%4,%5,%6,%7}, {%8,%9}, {%0,%1,%2,%3};"
        : "+f"(d.x), "+f"(d.y), "+f"(d.z), "+f"(d.w)
        : "r"(a0), "r"(a1), "r"(a2), "r"(a3), "r"(b0), "r"(b1));
}

// ---------------- tf32 tensor-core NT GEMM: C[M,N] = A[M,K] @ B[N,K]^T --------
// 128x128 tile, BK=16, double-buffered smem, 2 CTAs/SM for staging/MMA overlap.
#define TS 136
#define BKG 16
__global__ __launch_bounds__(256, 2) void sgemm_tf32(const float* __restrict__ A,
                                                     const float* __restrict__ B,
                                                     float* __restrict__ C,
                                                     int M, int N, int K) {
    __shared__ uint32_t As[2][BKG * TS];
    __shared__ uint32_t Bs[2][BKG * TS];

    const int tid  = threadIdx.x;
    const int lane = tid & 31;
    const int wid  = tid >> 5;
    const int warp_m = (wid & 1) * 64;
    const int warp_n = (wid >> 1) * 32;
    const int row0 = blockIdx.y * 128;
    const int col0 = blockIdx.x * 128;

    const int kr = lane & 3;
    const int mr = lane >> 2;

    float4 acc[4][4];
#pragma unroll
    for (int i = 0; i < 4; i++)
#pragma unroll
        for (int j = 0; j < 4; j++) acc[i][j] = make_float4(0.f, 0.f, 0.f, 0.f);

    const int lr = tid >> 1;           // 0..127
    const int lk = (tid & 1) * 8;      // 0 or 8
    const bool aval = (row0 + lr) < M;
    const bool bval = (col0 + lr) < N;
    const float* Aptr = A + (size_t)(row0 + lr) * K + lk;
    const float* Bptr = B + (size_t)(col0 + lr) * K + lk;
    const float4 z4 = make_float4(0.f, 0.f, 0.f, 0.f);

    // preload tile 0
    {
        float4 av0 = aval ? *(const float4*)(Aptr)     : z4;
        float4 av1 = aval ? *(const float4*)(Aptr + 4) : z4;
        float4 bv0 = bval ? *(const float4*)(Bptr)     : z4;
        float4 bv1 = bval ? *(const float4*)(Bptr + 4) : z4;
        As[0][(lk + 0) * TS + lr] = f2tf32(av0.x);
        As[0][(lk + 1) * TS + lr] = f2tf32(av0.y);
        As[0][(lk + 2) * TS + lr] = f2tf32(av0.z);
        As[0][(lk + 3) * TS + lr] = f2tf32(av0.w);
        As[0][(lk + 4) * TS + lr] = f2tf32(av1.x);
        As[0][(lk + 5) * TS + lr] = f2tf32(av1.y);
        As[0][(lk + 6) * TS + lr] = f2tf32(av1.z);
        As[0][(lk + 7) * TS + lr] = f2tf32(av1.w);
        Bs[0][(lk + 0) * TS + lr] = f2tf32(bv0.x);
        Bs[0][(lk + 1) * TS + lr] = f2tf32(bv0.y);
        Bs[0][(lk + 2) * TS + lr] = f2tf32(bv0.z);
        Bs[0][(lk + 3) * TS + lr] = f2tf32(bv0.w);
        Bs[0][(lk + 4) * TS + lr] = f2tf32(bv1.x);
        Bs[0][(lk + 5) * TS + lr] = f2tf32(bv1.y);
        Bs[0][(lk + 6) * TS + lr] = f2tf32(bv1.z);
        Bs[0][(lk + 7) * TS + lr] = f2tf32(bv1.w);
    }
    __syncthreads();

    int cur = 0;
    for (int k0 = 0; k0 < K; k0 += BKG) {
        const bool has_next = (k0 + BKG) < K;
        float4 nav0, nav1, nbv0, nbv1;
        if (has_next) {
            nav0 = aval ? *(const float4*)(Aptr + k0 + BKG)     : z4;
            nav1 = aval ? *(const float4*)(Aptr + k0 + BKG + 4) : z4;
            nbv0 = bval ? *(const float4*)(Bptr + k0 + BKG)     : z4;
            nbv1 = bval ? *(const float4*)(Bptr + k0 + BKG + 4) : z4;
        }

#pragma unroll
        for (int half = 0; half < 2; half++) {
            const int kb8 = half * 8;
            uint32_t a[4][4];
#pragma unroll
            for (int ma = 0; ma < 4; ma++) {
                const int base = warp_m + ma * 16 + mr;
                a[ma][0] = As[cur][(kb8 + kr) * TS + base];
                a[ma][1] = As[cur][(kb8 + kr) * TS + base + 8];
                a[ma][2] = As[cur][(kb8 + kr + 4) * TS + base];
                a[ma][3] = As[cur][(kb8 + kr + 4) * TS + base + 8];
            }
            uint32_t b[4][2];
#pragma unroll
            for (int nb = 0; nb < 4; nb++) {
                const int nbase = warp_n + nb * 8 + mr;
                b[nb][0] = Bs[cur][(kb8 + kr) * TS + nbase];
                b[nb][1] = Bs[cur][(kb8 + kr + 4) * TS + nbase];
            }
#pragma unroll
            for (int ma = 0; ma < 4; ma++)
#pragma unroll
                for (int nb = 0; nb < 4; nb++)
                    mma_tf32(acc[ma][nb], a[ma][0], a[ma][1], a[ma][2], a[ma][3],
                             b[nb][0], b[nb][1]);
        }

        if (has_next) {
            const int nxt = cur ^ 1;
            As[nxt][(lk + 0) * TS + lr] = f2tf32(nav0.x);
            As[nxt][(lk + 1) * TS + lr] = f2tf32(nav0.y);
            As[nxt][(lk + 2) * TS + lr] = f2tf32(nav0.z);
            As[nxt][(lk + 3) * TS + lr] = f2tf32(nav0.w);
            As[nxt][(lk + 4) * TS + lr] = f2tf32(nav1.x);
            As[nxt][(lk + 5) * TS + lr] = f2tf32(nav1.y);
            As[nxt][(lk + 6) * TS + lr] = f2tf32(nav1.z);
            As[nxt][(lk + 7) * TS + lr] = f2tf32(nav1.w);
            Bs[nxt][(lk + 0) * TS + lr] = f2tf32(nbv0.x);
            Bs[nxt][(lk + 1) * TS + lr] = f2tf32(nbv0.y);
            Bs[nxt][(lk + 2) * TS + lr] = f2tf32(nbv0.z);
            Bs[nxt][(lk + 3) * TS + lr] = f2tf32(nbv0.w);
            Bs[nxt][(lk + 4) * TS + lr] = f2tf32(nbv1.x);
            Bs[nxt][(lk + 5) * TS + lr] = f2tf32(nbv1.y);
            Bs[nxt][(lk + 6) * TS + lr] = f2tf32(nbv1.z);
            Bs[nxt][(lk + 7) * TS + lr] = f2tf32(nbv1.w);
            __syncthreads();
            cur = nxt;
        }
    }

#pragma unroll
    for (int ma = 0; ma < 4; ma++) {
        const int r = row0 + warp_m + ma * 16 + (lane >> 2);
        if (r >= M) continue;
#pragma unroll
        for (int nb = 0; nb < 4; nb++) {
            const int c = col0 + warp_n + nb * 8 + 2 * (lane & 3);
            if (c < N) {
                float* p0 = C + (size_t)r * N + c;
                p0[0] = acc[ma][nb].x;
                p0[1] = acc[ma][nb].y;
                float* p1 = p0 + (size_t)8 * N;
                p1[0] = acc[ma][nb].z;
                p1[1] = acc[ma][nb].w;
            }
        }
    }
}

// ---------------- RMS norms ----------------
__global__ __launch_bounds__(256) void rms_q_kernel(float* __restrict__ x,
                                                    const float* __restrict__ w) {
    __shared__ float sbuf[256];
    const int row = blockIdx.x;
    float* p = x + (size_t)row * QLR;
    float ss = 0.0f;
    for (int d = threadIdx.x; d < QLR; d += 256) { float v = p[d]; ss += v * v; }
    sbuf[threadIdx.x] = ss;
    __syncthreads();
    if (threadIdx.x == 0) {
        float r = 0.0f;
        for (int i = 0; i < 256; i++) r += sbuf[i];
        sbuf[0] = r;
    }
    __syncthreads();
    const float inv = rsqrtf(sbuf[0] * (1.0f / QLR) + 1e-6f);
    for (int d = threadIdx.x; d < QLR; d += 256) p[d] = p[d] * inv * w[d];
}

__global__ __launch_bounds__(256) void rms_kv_kernel(const float* __restrict__ xin,
                                                     const float* __restrict__ w,
                                                     float* __restrict__ xout) {
    __shared__ float sbuf[256];
    const int row = blockIdx.x;
    const float* p = xin + (size_t)row * (KVLR + ROPEDIM);
    float ss = 0.0f;
    for (int d = threadIdx.x; d < KVLR; d += 256) { float v = p[d]; ss += v * v; }
    sbuf[threadIdx.x] = ss;
    __syncthreads();
    if (threadIdx.x == 0) {
        float r = 0.0f;
        for (int i = 0; i < 256; i++) r += sbuf[i];
        sbuf[0] = r;
    }
    __syncthreads();
    const float inv = rsqrtf(sbuf[0] * (1.0f / KVLR) + 1e-6f);
    float* o = xout + (size_t)row * KVLR;
    for (int d = threadIdx.x; d < KVLR; d += 256) o[d] = p[d] * inv * w[d];
}

// ---------------- RoPE: half-split pairing, NEGATED rotation sign (validated R8)
__device__ __forceinline__ float rope_invfreq(int j) {
    return exp2f(-(float)j * (13.287712379549449f / 32.0f));
}

__global__ void rope_q_kernel(float* __restrict__ q) {
    const int t = blockIdx.x;
    const int h = threadIdx.x >> 5;
    const int j = threadIdx.x & 31;
    float* base = q + (size_t)t * (NH * QHD) + h * QHD + NOPE;
    float c, s;
    sincosf((float)t * rope_invfreq(j), &c, &s);
    const float x0 = base[j];
    const float x1 = base[j + 32];
    base[j]      = x0 * c + x1 * s;
    base[j + 32] = x1 * c - x0 * s;
}

__global__ void rope_k_kernel(const float* __restrict__ kvlatpe, float* __restrict__ kpe) {
    const int t = blockIdx.x;
    const int j = threadIdx.x;
    const float* base = kvlatpe + (size_t)t * (KVLR + ROPEDIM) + KVLR;
    float c, s;
    sincosf((float)t * rope_invfreq(j), &c, &s);
    const float x0 = base[j];
    const float x1 = base[j + 32];
    kpe[(size_t)t * ROPEDIM + j]      = x0 * c + x1 * s;
    kpe[(size_t)t * ROPEDIM + j + 32] = x1 * c - x0 * s;
}

// ---------------- Flash attention: tensor-core S (tf32x2) + PV (tf32) ---------
// Q pre-split into hi/lo tf32 at staging; K split on the fly.
// Softmax: 4 threads per row (quad shfl reduce).
#define FQ 200
#define FV 136
#define FP 68
#define F_QH 0
#define F_QL (F_QH + 64 * FQ)
#define F_KS (F_QL + 64 * FQ)
#define F_VS (F_KS + 64 * FQ)
#define F_PS (F_VS + 64 * FV)
#define F_MS (F_PS + 64 * FP)
#define F_LS (F_MS + 64)
#define F_CS (F_LS + 64)
#define FLASH_SMEM_WORDS (F_CS + 64)
#define FLASH_SMEM_BYTES (FLASH_SMEM_WORDS * 4)

__global__ __launch_bounds__(256) void flash_kernel(const float* __restrict__ q,
                                                    const float* __restrict__ kv,
                                                    const float* __restrict__ kpe,
                                                    float* __restrict__ attn) {
    extern __shared__ __align__(16) float sm[];
    uint32_t* Qhi = (uint32_t*)(sm + F_QH);
    uint32_t* Qlo = (uint32_t*)(sm + F_QL);
    float*    Ks  = sm + F_KS;
    uint32_t* Vs  = (uint32_t*)(sm + F_VS);
    float*    Ps  = sm + F_PS;
    float*    m_s = sm + F_MS;
    float*    l_s = sm + F_LS;
    float*    c_s = sm + F_CS;

    const int tid  = threadIdx.x;
    const int lane = tid & 31;
    const int wid  = tid >> 5;
    const int kr = lane & 3;
    const int mr = lane >> 2;
    const int qb = blockIdx.x;
    const int h  = blockIdx.y;
    const int qbase = qb * 64;
    const float scale = 0.07216878364870323f;  // 192^-0.5

    const int s_wm = (wid & 1) * 32;
    const int s_wn = (wid >> 1) * 16;
    const int p_wm = (wid & 1) * 32;
    const int p_wn = (wid >> 1) * 32;

    // stage Q once: pre-split hi/lo
    for (int idx = tid; idx < 64 * 192; idx += 256) {
        int r = idx / 192, d = idx - r * 192;
        float val = q[(size_t)(qbase + r) * (NH * QHD) + h * QHD + d] * scale;
        uint32_t hi, lo;
        split_tf32(val, hi, lo);
        Qhi[r * FQ + d] = hi;
        Qlo[r * FQ + d] = lo;
    }
    if (tid < 64) { m_s[tid] = -1e30f; l_s[tid] = 0.0f; }

    float4 acc[2][4];
#pragma unroll
    for (int i = 0; i < 2; i++)
#pragma unroll
        for (int j = 0; j < 4; j++) acc[i][j] = make_float4(0.f, 0.f, 0.f, 0.f);

    for (int kb = 0; kb <= qb; kb++) {
        const int kbase = kb * 64;
        __syncthreads();
        for (int idx = tid; idx < 64 * 192; idx += 256) {
            int c = idx / 192, d = idx - c * 192;
            float v = (d < NOPE)
                ? kv[(size_t)(kbase + c) * (NH * (NOPE + VHD)) + h * (NOPE + VHD) + d]
                : kpe[(size_t)(kbase + c) * ROPEDIM + (d - NOPE)];
            Ks[c * FQ + d] = v;
        }
        for (int idx = tid; idx < 64 * 128; idx += 256) {
            int c = idx >> 7, d = idx & 127;
            Vs[c * FV + d] = f2tf32(
                kv[(size_t)(kbase + c) * (NH * (NOPE + VHD)) + h * (NOPE + VHD) + NOPE + d]);
        }
        __syncthreads();

        // ---- S = Q K^T via tf32x2 (hi/lo), fp32 accumulate ----
        float4 sc[2][2];
#pragma unroll
        for (int i = 0; i < 2; i++)
#pragma unroll
            for (int j = 0; j < 2; j++) sc[i][j] = make_float4(0.f, 0.f, 0.f, 0.f);

        for (int k0 = 0; k0 < 192; k0 += 8) {
            uint32_t ah[2][4], al[2][4];
#pragma unroll
            for (int ma = 0; ma < 2; ma++) {
                const int r0 = s_wm + ma * 16 + mr;
                const int b0 = r0 * FQ + k0 + kr;
                ah[ma][0] = Qhi[b0];               al[ma][0] = Qlo[b0];
                ah[ma][1] = Qhi[b0 + 8 * FQ];      al[ma][1] = Qlo[b0 + 8 * FQ];
                ah[ma][2] = Qhi[b0 + 4];           al[ma][2] = Qlo[b0 + 4];
                ah[ma][3] = Qhi[b0 + 8 * FQ + 4];  al[ma][3] = Qlo[b0 + 8 * FQ + 4];
            }
            uint32_t bh[2][2], bl[2][2];
#pragma unroll
            for (int nb = 0; nb < 2; nb++) {
                const int n0 = s_wn + nb * 8 + mr;
                split_tf32(Ks[n0 * FQ + k0 + kr],     bh[nb][0], bl[nb][0]);
                split_tf32(Ks[n0 * FQ + k0 + kr + 4], bh[nb][1], bl[nb][1]);
            }
#pragma unroll
            for (int ma = 0; ma < 2; ma++)
#pragma unroll
                for (int nb = 0; nb < 2; nb++) {
                    mma_tf32(sc[ma][nb], ah[ma][0], ah[ma][1], ah[ma][2], ah[ma][3],
                             bh[nb][0], bh[nb][1]);
                    mma_tf32(sc[ma][nb], al[ma][0], al[ma][1], al[ma][2], al[ma][3],
                             bh[nb][0], bh[nb][1]);
                    mma_tf32(sc[ma][nb], ah[ma][0], ah[ma][1], ah[ma][2], ah[ma][3],
                             bl[nb][0], bl[nb][1]);
                }
        }

        // mask diagonal tile + write scores to Ps
#pragma unroll
        for (int ma = 0; ma < 2; ma++) {
            const int r0 = s_wm + ma * 16 + (lane >> 2);
#pragma unroll
            for (int nb = 0; nb < 2; nb++) {
                const int c0 = s_wn + nb * 8 + 2 * (lane & 3);
                float4 v = sc[ma][nb];
                if (kb == qb) {
                    if (c0 > r0)         v.x = -1e30f;
                    if (c0 + 1 > r0)     v.y = -1e30f;
                    if (c0 > r0 + 8)     v.z = -1e30f;
                    if (c0 + 1 > r0 + 8) v.w = -1e30f;
                }
                Ps[r0 * FP + c0]           = v.x;
                Ps[r0 * FP + c0 + 1]       = v.y;
                Ps[(r0 + 8) * FP + c0]     = v.z;
                Ps[(r0 + 8) * FP + c0 + 1] = v.w;
            }
        }
        __syncthreads();

        // ---- per-row online softmax: 4 threads per row, quad shfl reduce ----
        {
            const int row = tid >> 2;      // 0..63
            const int sub = tid & 3;       // 0..3
            float mx = -1e30f;
#pragma unroll
            for (int i = 0; i < 16; i++) {
                float v = Ps[row * FP + sub + i * 4];
                mx = fmaxf(mx, v);
            }
            mx = fmaxf(mx, __shfl_xor_sync(0xffffffffu, mx, 1));
            mx = fmaxf(mx, __shfl_xor_sync(0xffffffffu, mx, 2));
            const float mold = m_s[row];
            const float mnew = fmaxf(mold, mx);
            float rs = 0.0f;
#pragma unroll
            for (int i = 0; i < 16; i++) {
                float e = __expf(Ps[row * FP + sub + i * 4] - mnew);
                Ps[row * FP + sub + i * 4] = e;
                rs += e;
            }
            rs += __shfl_xor_sync(0xffffffffu, rs, 1);
            rs += __shfl_xor_sync(0xffffffffu, rs, 2);
            if (sub == 0) {
                const float corr = __expf(mold - mnew);
                l_s[row] = l_s[row] * corr + rs;
                m_s[row] = mnew;
                c_s[row] = corr;
            }
        }
        __syncthreads();

        // ---- acc = acc*corr + P @ V (single-pass tf32) ----
#pragma unroll
        for (int ma = 0; ma < 2; ma++) {
            const int r0 = p_wm + ma * 16 + (lane >> 2);
            const float c1 = c_s[r0];
            const float c2 = c_s[r0 + 8];
#pragma unroll
            for (int nb = 0; nb < 4; nb++) {
                acc[ma][nb].x *= c1; acc[ma][nb].y *= c1;
                acc[ma][nb].z *= c2; acc[ma][nb].w *= c2;
            }
        }
        for (int k0 = 0; k0 < 64; k0 += 8) {
            uint32_t a[2][4];
#pragma unroll
            for (int ma = 0; ma < 2; ma++) {
                const int r0 = p_wm + ma * 16 + mr;
                a[ma][0] = f2tf32(Ps[r0 * FP + k0 + kr]);
                a[ma][1] = f2tf32(Ps[(r0 + 8) * FP + k0 + kr]);
                a[ma][2] = f2tf32(Ps[r0 * FP + k0 + kr + 4]);
                a[ma][3] = f2tf32(Ps[(r0 + 8) * FP + k0 + kr + 4]);
            }
            uint32_t b[4][2];
#pragma unroll
            for (int nb = 0; nb < 4; nb++) {
                const int n0 = p_wn + nb * 8 + mr;
                b[nb][0] = Vs[(k0 + kr) * FV + n0];
                b[nb][1] = Vs[(k0 + kr + 4) * FV + n0];
            }
#pragma unroll
            for (int ma = 0; ma < 2; ma++)
#pragma unroll
                for (int nb = 0; nb < 4; nb++)
                    mma_tf32(acc[ma][nb], a[ma][0], a[ma][1], a[ma][2], a[ma][3],
                             b[nb][0], b[nb][1]);
        }
    }

    // epilogue: normalize by l and store
#pragma unroll
    for (int ma = 0; ma < 2; ma++) {
        const int r0 = p_wm + ma * 16 + (lane >> 2);
        const float inv1 = 1.0f / l_s[r0];
        const float inv2 = 1.0f / l_s[r0 + 8];
        const int t1 = qbase + r0;
        const int t2 = t1 + 8;
#pragma unroll
        for (int nb = 0; nb < 4; nb++) {
            const int c0 = p_wn + nb * 8 + 2 * (lane & 3);
            float* o1 = attn + (size_t)t1 * (NH * VHD) + h * VHD + c0;
            o1[0] = acc[ma][nb].x * inv1;
            o1[1] = acc[ma][nb].y * inv1;
            float* o2 = attn + (size_t)t2 * (NH * VHD) + h * VHD + c0;
            o2[0] = acc[ma][nb].z * inv2;
            o2[1] = acc[ma][nb].w * inv2;
        }
    }
}

// ---------------- launch ----------------
extern "C" void kernel_launch(void* const* d_in, const int* in_sizes, int n_in,
                              void* d_out, int out_size) {
    const float *hidden = nullptr, *q_a_w = nullptr, *q_a_ln_w = nullptr, *q_b_w = nullptr,
                *kv_a_w = nullptr, *kv_a_ln_w = nullptr, *kv_b_w = nullptr, *o_w = nullptr;
    for (int i = 0; i < n_in; i++) {
        const float* p = (const float*)d_in[i];
        switch (in_sizes[i]) {
            case QLR * HDIM:                q_a_w = p;    break;  // 3145728
            case QLR:                       q_a_ln_w = p; break;  // 1536
            case NH * QHD * QLR:            q_b_w = p;    break;  // 4718592
            case (KVLR + ROPEDIM) * HDIM:   kv_a_w = p;   break;  // 1179648
            case KVLR:                      kv_a_ln_w = p;break;  // 512
            case NH * (NOPE + VHD) * KVLR:  kv_b_w = p;   break;  // 2097152
            case SEQ * HDIM:  if (!hidden) hidden = p; else o_w = p; break; // 4194304 x2
        }
    }
    float* out = (float*)d_out;

    float* base = nullptr;
    cudaGetSymbolAddress((void**)&base, g_scratch);
    float* qlat    = base + OFF_QLAT;
    float* kvlatpe = base + OFF_KVLATPE;
    float* kvlat   = base + OFF_KVLAT;
    float* kpe     = base + OFF_KPE;
    float* qbuf    = base + OFF_Q;
    float* kvbuf   = base + OFF_KV;
    float* attnbuf = base + OFF_ATTN;

    cudaFuncSetAttribute(flash_kernel, cudaFuncAttributeMaxDynamicSharedMemorySize,
                         FLASH_SMEM_BYTES);

    sgemm_tf32<<<dim3(QLR / 128, SEQ / 128), 256>>>(hidden, q_a_w, qlat, SEQ, QLR, HDIM);
    sgemm_tf32<<<dim3((KVLR + ROPEDIM + 127) / 128, SEQ / 128), 256>>>(hidden, kv_a_w, kvlatpe,
                                                                       SEQ, KVLR + ROPEDIM, HDIM);
    rms_q_kernel<<<SEQ, 256>>>(qlat, q_a_ln_w);
    rms_kv_kernel<<<SEQ, 256>>>(kvlatpe, kv_a_ln_w, kvlat);
    rope_k_kernel<<<SEQ, 32>>>(kvlatpe, kpe);
    sgemm_tf32<<<dim3((NH * QHD) / 128, SEQ / 128), 256>>>(qlat, q_b_w, qbuf, SEQ, NH * QHD, QLR);
    sgemm_tf32<<<dim3((NH * (NOPE + VHD)) / 128, SEQ / 128), 256>>>(kvlat, kv_b_w, kvbuf,
                                                                    SEQ, NH * (NOPE + VHD), KVLR);
    rope_q_kernel<<<SEQ, 512>>>(qbuf);
    flash_kernel<<<dim3(SEQ / 64, NH), 256, FLASH_SMEM_BYTES>>>(qbuf, kvbuf, kpe, attnbuf);
    sgemm_tf32<<<dim3(HDIM / 128, SEQ / 128), 256>>>(attnbuf, o_w, out, SEQ, HDIM, NH * VHD);
}

// round 16
// speedup vs baseline: 1.3957x; 1.3957x over previous
#include <cuda_runtime.h>
#include <cuda_bf16.h>
#include <math.h>
#include <stdint.h>

#define SEQ   2048
#define HDIM  2048
#define NH    16
#define QLR   1536
#define KVLR  512
#define NOPE  128
#define ROPEDIM 64
#define VHD   128
#define QHD   192   // NOPE + ROPE

// ---------------- scratch arena (no allocations allowed) ----------------
#define OFF_QLAT    0
#define OFF_KVLATPE (OFF_QLAT    + SEQ*QLR)
#define OFF_KVLAT   (OFF_KVLATPE + SEQ*(KVLR+ROPEDIM))
#define OFF_KPE     (OFF_KVLAT   + SEQ*KVLR)
#define OFF_Q       (OFF_KPE     + SEQ*ROPEDIM)
#define OFF_KV      (OFF_Q       + SEQ*NH*QHD)
#define OFF_ATTN    (OFF_KV      + SEQ*NH*(NOPE+VHD))
#define SCRATCH_TOTAL (OFF_ATTN  + SEQ*NH*VHD)

__device__ float g_scratch[SCRATCH_TOTAL];

// ---------------- tf32 helpers ----------------
__device__ __forceinline__ uint32_t f2tf32(float x) {
    uint32_t r;
    asm("cvt.rna.tf32.f32 %0, %1;" : "=r"(r) : "f"(x));
    return r;
}

__device__ __forceinline__ void split_tf32(float x, uint32_t& hi, uint32_t& lo) {
    hi = f2tf32(x);
    lo = f2tf32(x - __uint_as_float(hi));
}

__device__ __forceinline__ void mma_tf32(float4& d,
                                         uint32_t a0, uint32_t a1, uint32_t a2, uint32_t a3,
                                         uint32_t b0, uint32_t b1) {
    asm volatile(
        "mma.sync.aligned.m16n8k8.row.col.f32.tf32.tf32.f32 "
        "{%0,%1,%2,%3}, {%4,%5,%6,%7}, {%8,%9}, {%0,%1,%2,%3};"
        : "+f"(d.x), "+f"(d.y), "+f"(d.z), "+f"(d.w)
        : "r"(a0), "r"(a1), "r"(a2), "r"(a3), "r"(b0), "r"(b1));
}

// ---------------- tf32 tensor-core NT GEMM: C[M,N] = A[M,K] @ B[N,K]^T --------
// 128x128 tile, BK=16, double-buffered smem, one sync/iter, 256 threads.
// (validated round 14 — 1 CTA/SM, no reg spills)
#define TS 136
#define BKG 16
__global__ __launch_bounds__(256) void sgemm_tf32(const float* __restrict__ A,
                                                  const float* __restrict__ B,
                                                  float* __restrict__ C,
                                                  int M, int N, int K) {
    __shared__ uint32_t As[2][BKG * TS];
    __shared__ uint32_t Bs[2][BKG * TS];

    const int tid  = threadIdx.x;
    const int lane = tid & 31;
    const int wid  = tid >> 5;
    const int warp_m = (wid & 1) * 64;
    const int warp_n = (wid >> 1) * 32;
    const int row0 = blockIdx.y * 128;
    const int col0 = blockIdx.x * 128;

    const int kr = lane & 3;
    const int mr = lane >> 2;

    float4 acc[4][4];
#pragma unroll
    for (int i = 0; i < 4; i++)
#pragma unroll
        for (int j = 0; j < 4; j++) acc[i][j] = make_float4(0.f, 0.f, 0.f, 0.f);

    const int lr = tid >> 1;           // 0..127
    const int lk = (tid & 1) * 8;      // 0 or 8
    const bool aval = (row0 + lr) < M;
    const bool bval = (col0 + lr) < N;
    const float* Aptr = A + (size_t)(row0 + lr) * K + lk;
    const float* Bptr = B + (size_t)(col0 + lr) * K + lk;
    const float4 z4 = make_float4(0.f, 0.f, 0.f, 0.f);

    // preload tile 0
    {
        float4 av0 = aval ? *(const float4*)(Aptr)     : z4;
        float4 av1 = aval ? *(const float4*)(Aptr + 4) : z4;
        float4 bv0 = bval ? *(const float4*)(Bptr)     : z4;
        float4 bv1 = bval ? *(const float4*)(Bptr + 4) : z4;
        As[0][(lk + 0) * TS + lr] = f2tf32(av0.x);
        As[0][(lk + 1) * TS + lr] = f2tf32(av0.y);
        As[0][(lk + 2) * TS + lr] = f2tf32(av0.z);
        As[0][(lk + 3) * TS + lr] = f2tf32(av0.w);
        As[0][(lk + 4) * TS + lr] = f2tf32(av1.x);
        As[0][(lk + 5) * TS + lr] = f2tf32(av1.y);
        As[0][(lk + 6) * TS + lr] = f2tf32(av1.z);
        As[0][(lk + 7) * TS + lr] = f2tf32(av1.w);
        Bs[0][(lk + 0) * TS + lr] = f2tf32(bv0.x);
        Bs[0][(lk + 1) * TS + lr] = f2tf32(bv0.y);
        Bs[0][(lk + 2) * TS + lr] = f2tf32(bv0.z);
        Bs[0][(lk + 3) * TS + lr] = f2tf32(bv0.w);
        Bs[0][(lk + 4) * TS + lr] = f2tf32(bv1.x);
        Bs[0][(lk + 5) * TS + lr] = f2tf32(bv1.y);
        Bs[0][(lk + 6) * TS + lr] = f2tf32(bv1.z);
        Bs[0][(lk + 7) * TS + lr] = f2tf32(bv1.w);
    }
    __syncthreads();

    int cur = 0;
    for (int k0 = 0; k0 < K; k0 += BKG) {
        const bool has_next = (k0 + BKG) < K;
        float4 nav0, nav1, nbv0, nbv1;
        if (has_next) {
            nav0 = aval ? *(const float4*)(Aptr + k0 + BKG)     : z4;
            nav1 = aval ? *(const float4*)(Aptr + k0 + BKG + 4) : z4;
            nbv0 = bval ? *(const float4*)(Bptr + k0 + BKG)     : z4;
            nbv1 = bval ? *(const float4*)(Bptr + k0 + BKG + 4) : z4;
        }

#pragma unroll
        for (int half = 0; half < 2; half++) {
            const int kb8 = half * 8;
            uint32_t a[4][4];
#pragma unroll
            for (int ma = 0; ma < 4; ma++) {
                const int base = warp_m + ma * 16 + mr;
                a[ma][0] = As[cur][(kb8 + kr) * TS + base];
                a[ma][1] = As[cur][(kb8 + kr) * TS + base + 8];
                a[ma][2] = As[cur][(kb8 + kr + 4) * TS + base];
                a[ma][3] = As[cur][(kb8 + kr + 4) * TS + base + 8];
            }
            uint32_t b[4][2];
#pragma unroll
            for (int nb = 0; nb < 4; nb++) {
                const int nbase = warp_n + nb * 8 + mr;
                b[nb][0] = Bs[cur][(kb8 + kr) * TS + nbase];
                b[nb][1] = Bs[cur][(kb8 + kr + 4) * TS + nbase];
            }
#pragma unroll
            for (int ma = 0; ma < 4; ma++)
#pragma unroll
                for (int nb = 0; nb < 4; nb++)
                    mma_tf32(acc[ma][nb], a[ma][0], a[ma][1], a[ma][2], a[ma][3],
                             b[nb][0], b[nb][1]);
        }

        if (has_next) {
            const int nxt = cur ^ 1;
            As[nxt][(lk + 0) * TS + lr] = f2tf32(nav0.x);
            As[nxt][(lk + 1) * TS + lr] = f2tf32(nav0.y);
            As[nxt][(lk + 2) * TS + lr] = f2tf32(nav0.z);
            As[nxt][(lk + 3) * TS + lr] = f2tf32(nav0.w);
            As[nxt][(lk + 4) * TS + lr] = f2tf32(nav1.x);
            As[nxt][(lk + 5) * TS + lr] = f2tf32(nav1.y);
            As[nxt][(lk + 6) * TS + lr] = f2tf32(nav1.z);
            As[nxt][(lk + 7) * TS + lr] = f2tf32(nav1.w);
            Bs[nxt][(lk + 0) * TS + lr] = f2tf32(nbv0.x);
            Bs[nxt][(lk + 1) * TS + lr] = f2tf32(nbv0.y);
            Bs[nxt][(lk + 2) * TS + lr] = f2tf32(nbv0.z);
            Bs[nxt][(lk + 3) * TS + lr] = f2tf32(nbv0.w);
            Bs[nxt][(lk + 4) * TS + lr] = f2tf32(nbv1.x);
            Bs[nxt][(lk + 5) * TS + lr] = f2tf32(nbv1.y);
            Bs[nxt][(lk + 6) * TS + lr] = f2tf32(nbv1.z);
            Bs[nxt][(lk + 7) * TS + lr] = f2tf32(nbv1.w);
            __syncthreads();
            cur = nxt;
        }
    }

#pragma unroll
    for (int ma = 0; ma < 4; ma++) {
        const int r = row0 + warp_m + ma * 16 + (lane >> 2);
        if (r >= M) continue;
#pragma unroll
        for (int nb = 0; nb < 4; nb++) {
            const int c = col0 + warp_n + nb * 8 + 2 * (lane & 3);
            if (c < N) {
                float* p0 = C + (size_t)r * N + c;
                p0[0] = acc[ma][nb].x;
                p0[1] = acc[ma][nb].y;
                float* p1 = p0 + (size_t)8 * N;
                p1[0] = acc[ma][nb].z;
                p1[1] = acc[ma][nb].w;
            }
        }
    }
}

// ---------------- RMS norms ----------------
__global__ __launch_bounds__(256) void rms_q_kernel(float* __restrict__ x,
                                                    const float* __restrict__ w) {
    __shared__ float sbuf[256];
    const int row = blockIdx.x;
    float* p = x + (size_t)row * QLR;
    float ss = 0.0f;
    for (int d = threadIdx.x; d < QLR; d += 256) { float v = p[d]; ss += v * v; }
    sbuf[threadIdx.x] = ss;
    __syncthreads();
    if (threadIdx.x == 0) {
        float r = 0.0f;
        for (int i = 0; i < 256; i++) r += sbuf[i];
        sbuf[0] = r;
    }
    __syncthreads();
    const float inv = rsqrtf(sbuf[0] * (1.0f / QLR) + 1e-6f);
    for (int d = threadIdx.x; d < QLR; d += 256) p[d] = p[d] * inv * w[d];
}

__global__ __launch_bounds__(256) void rms_kv_kernel(const float* __restrict__ xin,
                                                     const float* __restrict__ w,
                                                     float* __restrict__ xout) {
    __shared__ float sbuf[256];
    const int row = blockIdx.x;
    const float* p = xin + (size_t)row * (KVLR + ROPEDIM);
    float ss = 0.0f;
    for (int d = threadIdx.x; d < KVLR; d += 256) { float v = p[d]; ss += v * v; }
    sbuf[threadIdx.x] = ss;
    __syncthreads();
    if (threadIdx.x == 0) {
        float r = 0.0f;
        for (int i = 0; i < 256; i++) r += sbuf[i];
        sbuf[0] = r;
    }
    __syncthreads();
    const float inv = rsqrtf(sbuf[0] * (1.0f / KVLR) + 1e-6f);
    float* o = xout + (size_t)row * KVLR;
    for (int d = threadIdx.x; d < KVLR; d += 256) o[d] = p[d] * inv * w[d];
}

// ---------------- RoPE: half-split pairing, NEGATED rotation sign (validated R8)
__device__ __forceinline__ float rope_invfreq(int j) {
    return exp2f(-(float)j * (13.287712379549449f / 32.0f));
}

__global__ void rope_q_kernel(float* __restrict__ q) {
    const int t = blockIdx.x;
    const int h = threadIdx.x >> 5;
    const int j = threadIdx.x & 31;
    float* base = q + (size_t)t * (NH * QHD) + h * QHD + NOPE;
    float c, s;
    sincosf((float)t * rope_invfreq(j), &c, &s);
    const float x0 = base[j];
    const float x1 = base[j + 32];
    base[j]      = x0 * c + x1 * s;
    base[j + 32] = x1 * c - x0 * s;
}

__global__ void rope_k_kernel(const float* __restrict__ kvlatpe, float* __restrict__ kpe) {
    const int t = blockIdx.x;
    const int j = threadIdx.x;
    const float* base = kvlatpe + (size_t)t * (KVLR + ROPEDIM) + KVLR;
    float c, s;
    sincosf((float)t * rope_invfreq(j), &c, &s);
    const float x0 = base[j];
    const float x1 = base[j + 32];
    kpe[(size_t)t * ROPEDIM + j]      = x0 * c + x1 * s;
    kpe[(size_t)t * ROPEDIM + j + 32] = x1 * c - x0 * s;
}

// ---------------- Flash attention: tensor-core S (tf32x2) + PV (tf32) ---------
// Q pre-split into hi/lo tf32 at staging; K split on the fly.
// Softmax: 4 threads per row (quad shfl reduce) — validated round 15.
#define FQ 200
#define FV 136
#define FP 68
#define F_QH 0
#define F_QL (F_QH + 64 * FQ)
#define F_KS (F_QL + 64 * FQ)
#define F_VS (F_KS + 64 * FQ)
#define F_PS (F_VS + 64 * FV)
#define F_MS (F_PS + 64 * FP)
#define F_LS (F_MS + 64)
#define F_CS (F_LS + 64)
#define FLASH_SMEM_WORDS (F_CS + 64)
#define FLASH_SMEM_BYTES (FLASH_SMEM_WORDS * 4)

__global__ __launch_bounds__(256) void flash_kernel(const float* __restrict__ q,
                                                    const float* __restrict__ kv,
                                                    const float* __restrict__ kpe,
                                                    float* __restrict__ attn) {
    extern __shared__ __align__(16) float sm[];
    uint32_t* Qhi = (uint32_t*)(sm + F_QH);
    uint32_t* Qlo = (uint32_t*)(sm + F_QL);
    float*    Ks  = sm + F_KS;
    uint32_t* Vs  = (uint32_t*)(sm + F_VS);
    float*    Ps  = sm + F_PS;
    float*    m_s = sm + F_MS;
    float*    l_s = sm + F_LS;
    float*    c_s = sm + F_CS;

    const int tid  = threadIdx.x;
    const int lane = tid & 31;
    const int wid  = tid >> 5;
    const int kr = lane & 3;
    const int mr = lane >> 2;
    const int qb = blockIdx.x;
    const int h  = blockIdx.y;
    const int qbase = qb * 64;
    const float scale = 0.07216878364870323f;  // 192^-0.5

    const int s_wm = (wid & 1) * 32;
    const int s_wn = (wid >> 1) * 16;
    const int p_wm = (wid & 1) * 32;
    const int p_wn = (wid >> 1) * 32;

    // stage Q once: pre-split hi/lo
    for (int idx = tid; idx < 64 * 192; idx += 256) {
        int r = idx / 192, d = idx - r * 192;
        float val = q[(size_t)(qbase + r) * (NH * QHD) + h * QHD + d] * scale;
        uint32_t hi, lo;
        split_tf32(val, hi, lo);
        Qhi[r * FQ + d] = hi;
        Qlo[r * FQ + d] = lo;
    }
    if (tid < 64) { m_s[tid] = -1e30f; l_s[tid] = 0.0f; }

    float4 acc[2][4];
#pragma unroll
    for (int i = 0; i < 2; i++)
#pragma unroll
        for (int j = 0; j < 4; j++) acc[i][j] = make_float4(0.f, 0.f, 0.f, 0.f);

    for (int kb = 0; kb <= qb; kb++) {
        const int kbase = kb * 64;
        __syncthreads();
        for (int idx = tid; idx < 64 * 192; idx += 256) {
            int c = idx / 192, d = idx - c * 192;
            float v = (d < NOPE)
                ? kv[(size_t)(kbase + c) * (NH * (NOPE + VHD)) + h * (NOPE + VHD) + d]
                : kpe[(size_t)(kbase + c) * ROPEDIM + (d - NOPE)];
            Ks[c * FQ + d] = v;
        }
        for (int idx = tid; idx < 64 * 128; idx += 256) {
            int c = idx >> 7, d = idx & 127;
            Vs[c * FV + d] = f2tf32(
                kv[(size_t)(kbase + c) * (NH * (NOPE + VHD)) + h * (NOPE + VHD) + NOPE + d]);
        }
        __syncthreads();

        // ---- S = Q K^T via tf32x2 (hi/lo), fp32 accumulate ----
        float4 sc[2][2];
#pragma unroll
        for (int i = 0; i < 2; i++)
#pragma unroll
            for (int j = 0; j < 2; j++) sc[i][j] = make_float4(0.f, 0.f, 0.f, 0.f);

        for (int k0 = 0; k0 < 192; k0 += 8) {
            uint32_t ah[2][4], al[2][4];
#pragma unroll
            for (int ma = 0; ma < 2; ma++) {
                const int r0 = s_wm + ma * 16 + mr;
                const int b0 = r0 * FQ + k0 + kr;
                ah[ma][0] = Qhi[b0];               al[ma][0] = Qlo[b0];
                ah[ma][1] = Qhi[b0 + 8 * FQ];      al[ma][1] = Qlo[b0 + 8 * FQ];
                ah[ma][2] = Qhi[b0 + 4];           al[ma][2] = Qlo[b0 + 4];
                ah[ma][3] = Qhi[b0 + 8 * FQ + 4];  al[ma][3] = Qlo[b0 + 8 * FQ + 4];
            }
            uint32_t bh[2][2], bl[2][2];
#pragma unroll
            for (int nb = 0; nb < 2; nb++) {
                const int n0 = s_wn + nb * 8 + mr;
                split_tf32(Ks[n0 * FQ + k0 + kr],     bh[nb][0], bl[nb][0]);
                split_tf32(Ks[n0 * FQ + k0 + kr + 4], bh[nb][1], bl[nb][1]);
            }
#pragma unroll
            for (int ma = 0; ma < 2; ma++)
#pragma unroll
                for (int nb = 0; nb < 2; nb++) {
                    mma_tf32(sc[ma][nb], ah[ma][0], ah[ma][1], ah[ma][2], ah[ma][3],
                             bh[nb][0], bh[nb][1]);
                    mma_tf32(sc[ma][nb], al[ma][0], al[ma][1], al[ma][2], al[ma][3],
                             bh[nb][0], bh[nb][1]);
                    mma_tf32(sc[ma][nb], ah[ma][0], ah[ma][1], ah[ma][2], ah[ma][3],
                             bl[nb][0], bl[nb][1]);
                }
        }

        // mask diagonal tile + write scores to Ps
#pragma unroll
        for (int ma = 0; ma < 2; ma++) {
            const int r0 = s_wm + ma * 16 + (lane >> 2);
#pragma unroll
            for (int nb = 0; nb < 2; nb++) {
                const int c0 = s_wn + nb * 8 + 2 * (lane & 3);
                float4 v = sc[ma][nb];
                if (kb == qb) {
                    if (c0 > r0)         v.x = -1e30f;
                    if (c0 + 1 > r0)     v.y = -1e30f;
                    if (c0 > r0 + 8)     v.z = -1e30f;
                    if (c0 + 1 > r0 + 8) v.w = -1e30f;
                }
                Ps[r0 * FP + c0]           = v.x;
                Ps[r0 * FP + c0 + 1]       = v.y;
                Ps[(r0 + 8) * FP + c0]     = v.z;
                Ps[(r0 + 8) * FP + c0 + 1] = v.w;
            }
        }
        __syncthreads();

        // ---- per-row online softmax: 4 threads per row, quad shfl reduce ----
        {
            const int row = tid >> 2;      // 0..63
            const int sub = tid & 3;       // 0..3
            float mx = -1e30f;
#pragma unroll
            for (int i = 0; i < 16; i++) {
                float v = Ps[row * FP + sub + i * 4];
                mx = fmaxf(mx, v);
            }
            mx = fmaxf(mx, __shfl_xor_sync(0xffffffffu, mx, 1));
            mx = fmaxf(mx, __shfl_xor_sync(0xffffffffu, mx, 2));
            const float mold = m_s[row];
            const float mnew = fmaxf(mold, mx);
            float rs = 0.0f;
#pragma unroll
            for (int i = 0; i < 16; i++) {
                float e = __expf(Ps[row * FP + sub + i * 4] - mnew);
                Ps[row * FP + sub + i * 4] = e;
                rs += e;
            }
            rs += __shfl_xor_sync(0xffffffffu, rs, 1);
            rs += __shfl_xor_sync(0xffffffffu, rs, 2);
            if (sub == 0) {
                const float corr = __expf(mold - mnew);
                l_s[row] = l_s[row] * corr + rs;
                m_s[row] = mnew;
                c_s[row] = corr;
            }
        }
        __syncthreads();

        // ---- acc = acc*corr + P @ V (single-pass tf32) ----
#pragma unroll
        for (int ma = 0; ma < 2; ma++) {
            const int r0 = p_wm + ma * 16 + (lane >> 2);
            const float c1 = c_s[r0];
            const float c2 = c_s[r0 + 8];
#pragma unroll
            for (int nb = 0; nb < 4; nb++) {
                acc[ma][nb].x *= c1; acc[ma][nb].y *= c1;
                acc[ma][nb].z *= c2; acc[ma][nb].w *= c2;
            }
        }
        for (int k0 = 0; k0 < 64; k0 += 8) {
            uint32_t a[2][4];
#pragma unroll
            for (int ma = 0; ma < 2; ma++) {
                const int r0 = p_wm + ma * 16 + mr;
                a[ma][0] = f2tf32(Ps[r0 * FP + k0 + kr]);
                a[ma][1] = f2tf32(Ps[(r0 + 8) * FP + k0 + kr]);
                a[ma][2] = f2tf32(Ps[r0 * FP + k0 + kr + 4]);
                a[ma][3] = f2tf32(Ps[(r0 + 8) * FP + k0 + kr + 4]);
            }
            uint32_t b[4][2];
#pragma unroll
            for (int nb = 0; nb < 4; nb++) {
                const int n0 = p_wn + nb * 8 + mr;
                b[nb][0] = Vs[(k0 + kr) * FV + n0];
                b[nb][1] = Vs[(k0 + kr + 4) * FV + n0];
            }
#pragma unroll
            for (int ma = 0; ma < 2; ma++)
#pragma unroll
                for (int nb = 0; nb < 4; nb++)
                    mma_tf32(acc[ma][nb], a[ma][0], a[ma][1], a[ma][2], a[ma][3],
                             b[nb][0], b[nb][1]);
        }
    }

    // epilogue: normalize by l and store
#pragma unroll
    for (int ma = 0; ma < 2; ma++) {
        const int r0 = p_wm + ma * 16 + (lane >> 2);
        const float inv1 = 1.0f / l_s[r0];
        const float inv2 = 1.0f / l_s[r0 + 8];
        const int t1 = qbase + r0;
        const int t2 = t1 + 8;
#pragma unroll
        for (int nb = 0; nb < 4; nb++) {
            const int c0 = p_wn + nb * 8 + 2 * (lane & 3);
            float* o1 = attn + (size_t)t1 * (NH * VHD) + h * VHD + c0;
            o1[0] = acc[ma][nb].x * inv1;
            o1[1] = acc[ma][nb].y * inv1;
            float* o2 = attn + (size_t)t2 * (NH * VHD) + h * VHD + c0;
            o2[0] = acc[ma][nb].z * inv2;
            o2[1] = acc[ma][nb].w * inv2;
        }
    }
}

// ---------------- launch ----------------
extern "C" void kernel_launch(void* const* d_in, const int* in_sizes, int n_in,
                              void* d_out, int out_size) {
    const float *hidden = nullptr, *q_a_w = nullptr, *q_a_ln_w = nullptr, *q_b_w = nullptr,
                *kv_a_w = nullptr, *kv_a_ln_w = nullptr, *kv_b_w = nullptr, *o_w = nullptr;
    for (int i = 0; i < n_in; i++) {
        const float* p = (const float*)d_in[i];
        switch (in_sizes[i]) {
            case QLR * HDIM:                q_a_w = p;    break;  // 3145728
            case QLR:                       q_a_ln_w = p; break;  // 1536
            case NH * QHD * QLR:            q_b_w = p;    break;  // 4718592
            case (KVLR + ROPEDIM) * HDIM:   kv_a_w = p;   break;  // 1179648
            case KVLR:                      kv_a_ln_w = p;break;  // 512
            case NH * (NOPE + VHD) * KVLR:  kv_b_w = p;   break;  // 2097152
            case SEQ * HDIM:  if (!hidden) hidden = p; else o_w = p; break; // 4194304 x2
        }
    }
    float* out = (float*)d_out;

    float* base = nullptr;
    cudaGetSymbolAddress((void**)&base, g_scratch);
    float* qlat    = base + OFF_QLAT;
    float* kvlatpe = base + OFF_KVLATPE;
    float* kvlat   = base + OFF_KVLAT;
    float* kpe     = base + OFF_KPE;
    float* qbuf    = base + OFF_Q;
    float* kvbuf   = base + OFF_KV;
    float* attnbuf = base + OFF_ATTN;

    cudaFuncSetAttribute(flash_kernel, cudaFuncAttributeMaxDynamicSharedMemorySize,
                         FLASH_SMEM_BYTES);

    sgemm_tf32<<<dim3(QLR / 128, SEQ / 128), 256>>>(hidden, q_a_w, qlat, SEQ, QLR, HDIM);
    sgemm_tf32<<<dim3((KVLR + ROPEDIM + 127) / 128, SEQ / 128), 256>>>(hidden, kv_a_w, kvlatpe,
                                                                       SEQ, KVLR + ROPEDIM, HDIM);
    rms_q_kernel<<<SEQ, 256>>>(qlat, q_a_ln_w);
    rms_kv_kernel<<<SEQ, 256>>>(kvlatpe, kv_a_ln_w, kvlat);
    rope_k_kernel<<<SEQ, 32>>>(kvlatpe, kpe);
    sgemm_tf32<<<dim3((NH * QHD) / 128, SEQ / 128), 256>>>(qlat, q_b_w, qbuf, SEQ, NH * QHD, QLR);
    sgemm_tf32<<<dim3((NH * (NOPE + VHD)) / 128, SEQ / 128), 256>>>(kvlat, kv_b_w, kvbuf,
                                                                    SEQ, NH * (NOPE + VHD), KVLR);
    rope_q_kernel<<<SEQ, 512>>>(qbuf);
    flash_kernel<<<dim3(SEQ / 64, NH), 256, FLASH_SMEM_BYTES>>>(qbuf, kvbuf, kpe, attnbuf);
    sgemm_tf32<<<dim3(HDIM / 128, SEQ / 128), 256>>>(attnbuf, o_w, out, SEQ, HDIM, NH * VHD);
}